// round 7
// baseline (speedup 1.0000x reference)
#include <cuda_runtime.h>
#include <cstdint>

// Problem constants
#define B_ 32
#define T_ 1024
#define D_ 256
#define H_ 256
#define NS 32                 // 32-row items: B_*NS = 1024 phase-1 work items

// Scratch (allocation-free rule: __device__ globals)
__device__ float g_part[B_ * NS * D_];   // partial t-sums (1 MB)
__device__ float g_W[B_ * D_];
__device__ float g_bv[B_ * D_];

// Grid-barrier state. Sense-reversing: g_cnt returns to 0 after every barrier,
// g_sense is monotonically increasing (wraps at 2^32) -> safe across graph replays.
__device__ unsigned g_cnt   = 0;
__device__ unsigned g_sense = 0;

__device__ __forceinline__ void grid_barrier(int S)
{
    __syncthreads();
    if (threadIdx.x == 0) {
        __threadfence();                            // make phase data visible
        unsigned s = atomicAdd(&g_sense, 0u);       // capture sense BEFORE arriving
        unsigned a = atomicAdd(&g_cnt, 1u);
        if (a == (unsigned)(S - 1)) {
            atomicExch(&g_cnt, 0u);                 // reset for next barrier
            __threadfence();
            atomicAdd(&g_sense, 1u);                // release
        } else {
            while (atomicAdd(&g_sense, 0u) == s) { __nanosleep(32); }
        }
        __threadfence();
    }
    __syncthreads();
}

__device__ __forceinline__ float4 add4(float4 a, float4 b)
{
    return make_float4(a.x + b.x, a.y + b.y, a.z + b.z, a.w + b.w);
}

// ---------------------------------------------------------------------------
// One persistent kernel, three phases separated by grid barriers.
// grid = S (#SMs), block = 1024 -> guaranteed co-resident (1 CTA/SM).
// ---------------------------------------------------------------------------
__global__ void __launch_bounds__(1024, 1) fused(
    const float* __restrict__ x,   const int* __restrict__ len,
    const float* __restrict__ w1w, const float* __restrict__ w1b,
    const float* __restrict__ w2w, const float* __restrict__ w2b,
    const float* __restrict__ v1w, const float* __restrict__ v1b,
    const float* __restrict__ v2w, const float* __restrict__ v2b,
    float* __restrict__ out, int S)
{
    __shared__ float4 smbuf[16 * 64];   // 16 KB, reused by phase 1 and phase 2
    const int tid = threadIdx.x;
    const int bid = blockIdx.x;

    // ======================= Phase 1: partial t-sums ========================
    // Item w covers flattened rows [w*32, w*32+32); g_part index == w.
    // Thread (tx in [0,64): d4, ty in [0,16)): rows ty and ty+16 -> 2 LDG.128.
    // Next item's loads are prefetched before the smem reduce to hide latency.
    {
        const int tx = tid & 63;
        const int ty = tid >> 6;
        int  w    = bid;
        bool have = (w < B_ * NS);
        float4 v0, v1;
        if (have) {
            const float4* xp = reinterpret_cast<const float4*>(x) + (size_t)w * 2048;
            v0 = xp[ty * 64 + tx];
            v1 = xp[(ty + 16) * 64 + tx];
        }
        while (have) {
            const int  wn    = w + S;
            const bool haven = (wn < B_ * NS);
            smbuf[ty * 64 + tx] = add4(v0, v1);
            __syncthreads();
            if (haven) {   // prefetch next item while this one reduces
                const float4* xp = reinterpret_cast<const float4*>(x) + (size_t)wn * 2048;
                v0 = xp[ty * 64 + tx];
                v1 = xp[(ty + 16) * 64 + tx];
            }
            if (ty == 0) {
                float4 r = smbuf[tx];
#pragma unroll
                for (int p = 1; p < 16; p++)
                    r = add4(r, smbuf[p * 64 + tx]);
                reinterpret_cast<float4*>(g_part)[w * 64 + tx] = r;
            }
            __syncthreads();
            w = wn; have = haven;
        }
    }

    grid_barrier(S);

    // ======================= Phase 2: the two MLPs ==========================
    // Work item m in [0, 64): b = m>>1, sel = m&1. 1024 threads per item:
    // thread (j = tid&255, s = tid>>8 in [0,4)) splits every dot product 4-way.
    {
        float* c   = reinterpret_cast<float*>(smbuf);          // [256]
        float* h   = c + 256;                                  // [256]
        float* red = h + 256;                                  // [4][256]
        const int j = tid & 255;
        const int s = tid >> 8;

        for (int m = bid; m < 2 * B_; m += S) {
            const int b   = m >> 1;
            const int sel = m & 1;
            const float* W1 = sel ? v1w : w1w;
            const float* B1 = sel ? v1b : w1b;
            const float* W2 = sel ? v2w : w2w;
            const float* B2 = sel ? v2b : w2b;

            // c[j] = (sum of 32 partials)/len  (partials L2-resident)
            {
                float a = 0.f;
#pragma unroll
                for (int p = 0; p < 8; p++)
                    a += g_part[(b * NS + s * 8 + p) * D_ + j];
                red[s * 256 + j] = a;
            }
            __syncthreads();
            if (s == 0)
                c[j] = (red[j] + red[256 + j] + red[512 + j] + red[768 + j])
                       / (float)__ldg(&len[b]);
            __syncthreads();

            // layer 1: unit j, element chunk s*64..+64
            {
                const float4* row = reinterpret_cast<const float4*>(W1 + (size_t)j * D_) + s * 16;
                const float4* cv  = reinterpret_cast<const float4*>(c) + s * 16;
                float a = 0.f;
#pragma unroll
                for (int i = 0; i < 16; i++) {
                    float4 w = row[i], cc = cv[i];
                    a += w.x * cc.x + w.y * cc.y + w.z * cc.z + w.w * cc.w;
                }
                red[s * 256 + j] = a;
            }
            __syncthreads();
            if (s == 0) {
                float a = red[j] + red[256 + j] + red[512 + j] + red[768 + j] + B1[j];
                h[j] = 0.5f * a * (1.f + erff(a * 0.70710678118654752f));  // exact gelu
            }
            __syncthreads();

            // layer 2: output d = j, element chunk s*64..+64
            {
                const float4* row = reinterpret_cast<const float4*>(W2 + (size_t)j * H_) + s * 16;
                const float4* hv  = reinterpret_cast<const float4*>(h) + s * 16;
                float a = 0.f;
#pragma unroll
                for (int i = 0; i < 16; i++) {
                    float4 w = row[i], hh = hv[i];
                    a += w.x * hh.x + w.y * hh.y + w.z * hh.z + w.w * hh.w;
                }
                red[s * 256 + j] = a;
            }
            __syncthreads();
            if (s == 0) {
                float a = red[j] + red[256 + j] + red[512 + j] + red[768 + j] + B2[j];
                (sel ? g_bv : g_W)[b * D_ + j] = a;
            }
            __syncthreads();   // smem free before next item
        }
    }

    grid_barrier(S);

    // ======================= Phase 3: elementwise out =======================
    // out[b,t,d] = (t<L) ? (1+W[b,d])*x[b,t,d] + (t==0 ? bv[b,d] : 0) : 0
    // Warp-per-row (2 float4/lane); t<L is warp-uniform.
    {
        const int wid  = tid >> 5;
        const int lane = tid & 31;
        const float4* x4 = reinterpret_cast<const float4*>(x);
        float4*       o4 = reinterpret_cast<float4*>(out);

        for (int r = bid * 32 + wid; r < B_ * T_; r += S * 32) {
            const int t = r & (T_ - 1);
            const int b = r >> 10;
            const int L = __ldg(&len[b]);
            const size_t i0 = (size_t)r * 64 + lane;

            if (t < L) {
                float4 xa = x4[i0];
                float4 xb = x4[i0 + 32];
                float4 wa = reinterpret_cast<const float4*>(g_W)[b * 64 + lane];
                float4 wb = reinterpret_cast<const float4*>(g_W)[b * 64 + lane + 32];
                float4 va, vb;
                va.x = (1.f + wa.x) * xa.x;  va.y = (1.f + wa.y) * xa.y;
                va.z = (1.f + wa.z) * xa.z;  va.w = (1.f + wa.w) * xa.w;
                vb.x = (1.f + wb.x) * xb.x;  vb.y = (1.f + wb.y) * xb.y;
                vb.z = (1.f + wb.z) * xb.z;  vb.w = (1.f + wb.w) * xb.w;
                if (t == 0) {
                    float4 ba = reinterpret_cast<const float4*>(g_bv)[b * 64 + lane];
                    float4 bb = reinterpret_cast<const float4*>(g_bv)[b * 64 + lane + 32];
                    va = add4(va, ba);
                    vb = add4(vb, bb);
                }
                o4[i0]      = va;
                o4[i0 + 32] = vb;
            } else {
                float4 z = make_float4(0.f, 0.f, 0.f, 0.f);
                o4[i0]      = z;
                o4[i0 + 32] = z;
            }
        }
    }
}

// ---------------------------------------------------------------------------
extern "C" void kernel_launch(void* const* d_in, const int* in_sizes, int n_in,
                              void* d_out, int out_size)
{
    const float* x    = (const float*)d_in[0];
    const int*   len  = (const int*)  d_in[1];
    const float* w1w  = (const float*)d_in[2];
    const float* w1b  = (const float*)d_in[3];
    const float* w2w  = (const float*)d_in[4];
    const float* w2b  = (const float*)d_in[5];
    const float* v1w  = (const float*)d_in[6];
    const float* v1b  = (const float*)d_in[7];
    const float* v2w  = (const float*)d_in[8];
    const float* v2b  = (const float*)d_in[9];
    float* out = (float*)d_out;

    int dev = 0;
    cudaGetDevice(&dev);
    int S = 0;
    cudaDeviceGetAttribute(&S, cudaDevAttrMultiProcessorCount, dev);
    if (S <= 0) S = 148;   // defensive fallback

    fused<<<S, 1024>>>(x, len, w1w, w1b, w2w, w2b, v1w, v1b, v2w, v2b, out, S);
}

// round 10
// speedup vs baseline: 1.1938x; 1.1938x over previous
#include <cuda_runtime.h>
#include <cstdint>

// Problem constants
#define B_ 32
#define T_ 1024
#define D_ 256
#define H_ 256
#define NS 16                      // items per batch: 512 items x 64 t-rows

// Scratch (allocation-free rule: __device__ globals)
__device__ float g_part[B_ * NS * D_];   // 512 KB of partial t-sums
__device__ float g_W[B_ * D_];
__device__ float g_bv[B_ * D_];

__device__ __forceinline__ float4 add4(float4 a, float4 b)
{
    return make_float4(a.x + b.x, a.y + b.y, a.z + b.z, a.w + b.w);
}

// ---------------------------------------------------------------------------
// Kernel 1: partial t-sums. grid 512, block 256.
// Item w = 64 consecutive t-rows (all within one b; b = w/16).
// Thread (tx in [0,64): d4 column, ty in [0,4)): 16 rows as 2 front-batched
// groups of 8 independent LDG.128 with register accumulation between.
// ---------------------------------------------------------------------------
__global__ void __launch_bounds__(256) k_reduce(const float* __restrict__ x)
{
    const int w  = blockIdx.x;
    const int tx = threadIdx.x & 63;
    const int ty = threadIdx.x >> 6;

    const float4* xp = reinterpret_cast<const float4*>(x) + (size_t)w * (64 * 64);

    float4 acc = make_float4(0.f, 0.f, 0.f, 0.f);
#pragma unroll
    for (int half = 0; half < 2; half++) {
        float4 v[8];
#pragma unroll
        for (int k = 0; k < 8; k++)
            v[k] = xp[(half * 32 + ty + 4 * k) * 64 + tx];
        float4 s0 = add4(add4(v[0], v[1]), add4(v[2], v[3]));
        float4 s1 = add4(add4(v[4], v[5]), add4(v[6], v[7]));
        acc = add4(acc, add4(s0, s1));
    }

    __shared__ float4 sm[4][64];
    sm[ty][tx] = acc;
    __syncthreads();
    if (ty == 0) {
        float4 r = add4(add4(sm[0][tx], sm[1][tx]), add4(sm[2][tx], sm[3][tx]));
        reinterpret_cast<float4*>(g_part)[w * 64 + tx] = r;
    }
}

// ---------------------------------------------------------------------------
// Kernel 2: the two MLPs. grid (B, 2), block 256. PDL secondary:
// warms all four weight matrices into L2 BEFORE the dependency sync
// (weights are inputs, independent of k_reduce), then syncs and computes.
// ---------------------------------------------------------------------------
__global__ void __launch_bounds__(256) k_mlp(
    const int* __restrict__ len,
    const float* __restrict__ w1w, const float* __restrict__ w1b,
    const float* __restrict__ w2w, const float* __restrict__ w2b,
    const float* __restrict__ v1w, const float* __restrict__ v1b,
    const float* __restrict__ v2w, const float* __restrict__ v2b)
{
    const int b   = blockIdx.x;
    const int sel = blockIdx.y;
    const float* W1 = sel ? v1w : w1w;
    const float* B1 = sel ? v1b : w1b;
    const float* W2 = sel ? v2w : w2w;
    const float* B2 = sel ? v2b : w2b;

    const int j = threadIdx.x;

    // ---- pre-sync: warm this path's weights into L2 (512 KB / path) ----
    // Only 2 of the 64 CTAs per path need to do this; use b==0 and b==1 CTAs
    // to split the work, others skip straight to the sync.
    if (b < 4) {
        const char* base = (const char*)(b & 1 ? W2 : W1);
        // 256 KB = 2048 x 128B lines; 2 CTAs x 256 thr -> 4 lines per thread
        for (int i = (b >> 1) * 1024 + j; i < 2048; i += 2048)
            ;  // (loop shape kept trivial; real prefetch below)
#pragma unroll
        for (int k = 0; k < 4; k++) {
            const char* p = base + ((size_t)((b >> 1) * 1024 + j + k * 256) * 128);
            asm volatile("prefetch.global.L2 [%0];" :: "l"(p));
        }
    }

    cudaGridDependencySynchronize();   // wait for k_reduce results

    __shared__ float c[D_];
    __shared__ float h[H_];

    // finalize mean (partials L2-resident)
    {
        float s = 0.f;
#pragma unroll
        for (int p = 0; p < NS; p++)
            s += g_part[(b * NS + p) * D_ + j];
        c[j] = s / (float)__ldg(&len[b]);
    }
    __syncthreads();

    // layer 1
    {
        const float4* row = reinterpret_cast<const float4*>(W1 + (size_t)j * D_);
        const float4* cv  = reinterpret_cast<const float4*>(c);
        float acc = B1[j];
#pragma unroll 8
        for (int i = 0; i < D_ / 4; i++) {
            float4 w = row[i], cc = cv[i];
            acc += w.x * cc.x + w.y * cc.y + w.z * cc.z + w.w * cc.w;
        }
        h[j] = 0.5f * acc * (1.f + erff(acc * 0.70710678118654752f));  // exact gelu
    }
    __syncthreads();

    // layer 2
    {
        const float4* row = reinterpret_cast<const float4*>(W2 + (size_t)j * H_);
        const float4* hv  = reinterpret_cast<const float4*>(h);
        float acc = B2[j];
#pragma unroll 8
        for (int i = 0; i < H_ / 4; i++) {
            float4 w = row[i], hh = hv[i];
            acc += w.x * hh.x + w.y * hh.y + w.z * hh.z + w.w * hh.w;
        }
        (sel ? g_bv : g_W)[b * D_ + j] = acc;
    }
}

// ---------------------------------------------------------------------------
// Kernel 3: elementwise output, warp-per-row. PDL secondary:
// loads x (input, independent of mlp) BEFORE the dependency sync, so the
// first wave's x reads overlap the mlp kernel. Only g_W/g_bv reads are
// after the sync.
// out[b,t,d] = (t<L) ? (1+W[b,d])*x[b,t,d] + (t==0 ? bv[b,d] : 0) : 0
// ---------------------------------------------------------------------------
__global__ void __launch_bounds__(256) k_out(
    const float* __restrict__ x,
    const int* __restrict__ len,
    float* __restrict__ out)
{
    const int w    = threadIdx.x >> 5;
    const int lane = threadIdx.x & 31;
    const int row  = blockIdx.x * 8 + w;      // b*T + t
    const int t = row & (T_ - 1);
    const int b = row >> 10;

    const size_t i0 = (size_t)row * 64 + lane;
    const float4* x4 = reinterpret_cast<const float4*>(x);
    float4*       o4 = reinterpret_cast<float4*>(out);

    const int L = __ldg(&len[b]);
    const bool valid = (t < L);

    float4 xa, xb;
    if (valid) {                 // pre-sync loads: x/len independent of mlp
        xa = x4[i0];
        xb = x4[i0 + 32];
    }

    cudaGridDependencySynchronize();   // wait for g_W / g_bv

    if (valid) {
        float4 wa = reinterpret_cast<const float4*>(g_W)[b * 64 + lane];
        float4 wb = reinterpret_cast<const float4*>(g_W)[b * 64 + lane + 32];
        float4 va, vb;
        va.x = (1.f + wa.x) * xa.x;  va.y = (1.f + wa.y) * xa.y;
        va.z = (1.f + wa.z) * xa.z;  va.w = (1.f + wa.w) * xa.w;
        vb.x = (1.f + wb.x) * xb.x;  vb.y = (1.f + wb.y) * xb.y;
        vb.z = (1.f + wb.z) * xb.z;  vb.w = (1.f + wb.w) * xb.w;
        if (t == 0) {
            float4 ba = reinterpret_cast<const float4*>(g_bv)[b * 64 + lane];
            float4 bb = reinterpret_cast<const float4*>(g_bv)[b * 64 + lane + 32];
            va = add4(va, ba);
            vb = add4(vb, bb);
        }
        o4[i0]      = va;
        o4[i0 + 32] = vb;
    } else {
        float4 z = make_float4(0.f, 0.f, 0.f, 0.f);
        o4[i0]      = z;
        o4[i0 + 32] = z;
    }
}

// ---------------------------------------------------------------------------
extern "C" void kernel_launch(void* const* d_in, const int* in_sizes, int n_in,
                              void* d_out, int out_size)
{
    const float* x    = (const float*)d_in[0];
    const int*   len  = (const int*)  d_in[1];
    const float* w1w  = (const float*)d_in[2];
    const float* w1b  = (const float*)d_in[3];
    const float* w2w  = (const float*)d_in[4];
    const float* w2b  = (const float*)d_in[5];
    const float* v1w  = (const float*)d_in[6];
    const float* v1b  = (const float*)d_in[7];
    const float* v2w  = (const float*)d_in[8];
    const float* v2b  = (const float*)d_in[9];
    float* out = (float*)d_out;

    // Kernel 1: normal launch
    k_reduce<<<B_ * NS, 256>>>(x);

    // PDL attribute for the two dependent kernels
    cudaLaunchAttribute pdl;
    pdl.id = cudaLaunchAttributeProgrammaticStreamSerialization;
    pdl.val.programmaticStreamSerializationAllowed = 1;

    // Kernel 2: mlp (PDL secondary of k_reduce)
    {
        cudaLaunchConfig_t cfg = {};
        cfg.gridDim  = dim3(B_, 2);
        cfg.blockDim = dim3(256);
        cfg.attrs    = &pdl;
        cfg.numAttrs = 1;
        cudaLaunchKernelEx(&cfg, k_mlp, len, w1w, w1b, w2w, w2b,
                           v1w, v1b, v2w, v2b);
    }

    // Kernel 3: out (PDL secondary of k_mlp)
    {
        cudaLaunchConfig_t cfg = {};
        cfg.gridDim  = dim3(B_ * T_ / 8);
        cfg.blockDim = dim3(256);
        cfg.attrs    = &pdl;
        cfg.numAttrs = 1;
        cudaLaunchKernelEx(&cfg, k_out, x, len, out);
    }
}